// round 1
// baseline (speedup 1.0000x reference)
#include <cuda_runtime.h>
#include <math.h>

#define NN   50000
#define NE   800000
#define NF   64
#define NRBF 10
#define NG   512
#define NH   64

// ---------------- scratch (device globals: no allocs allowed) ----------------
__device__ float g_x[NN * NF];      // node features
__device__ float g_h[NN * NF];      // pre-message transform
__device__ float g_agg[NN * NF];    // scatter accumulator
__device__ float g_e[NE * NRBF];    // RBF expansion (precomputed once, reused 3x)
__device__ float g_gsum[NG * NF];   // per-graph sums
__device__ float g_gcnt[NG];        // per-graph counts

// ---------------- kernels ----------------

// x[n, :] = emb[x_ids[n], :]
__global__ void k_embed(const int* __restrict__ ids, const float* __restrict__ emb) {
    int t = blockIdx.x * blockDim.x + threadIdx.x;
    if (t >= NN * NF) return;
    int n = t >> 6, j = t & 63;
    g_x[t] = emb[ids[n] * NF + j];
}

// e[E, 10] = exp(-1.125 * (d - r*(6/9))^2)
__global__ void k_rbf(const float* __restrict__ ea) {
    int e = blockIdx.x * blockDim.x + threadIdx.x;
    if (e >= NE) return;
    float d = ea[e];
    const float step = 6.0f / 9.0f;
#pragma unroll
    for (int r = 0; r < NRBF; r++) {
        float t = d - step * (float)r;
        g_e[e * NRBF + r] = expf(-1.125f * t * t);
    }
}

// mode 0: g_h = g_x @ W + b         (also zeroes g_agg for the upcoming scatter)
// mode 1: g_x = softplus(g_x + g_agg @ W + b)
__global__ void k_node_gemm(const float* __restrict__ W, const float* __restrict__ b, int mode) {
    __shared__ float Ws[NF * NF];
    __shared__ float bs[NF];
    int tid = threadIdx.x;
    for (int i = tid; i < NF * NF; i += blockDim.x) Ws[i] = W[i];
    if (tid < NF) bs[tid] = b[tid];
    __syncthreads();

    int wid = tid >> 5, lane = tid & 31;
    int row = blockIdx.x * (blockDim.x >> 5) + wid;
    if (row >= NN) return;

    const float* in = mode ? (g_agg + (size_t)row * NF) : (g_x + (size_t)row * NF);
    float v0 = in[lane];
    float v1 = in[lane + 32];

    float a0 = bs[lane], a1 = bs[lane + 32];
#pragma unroll
    for (int k = 0; k < 32; k++) {
        float xk = __shfl_sync(0xffffffffu, v0, k);
        a0 += xk * Ws[k * NF + lane];
        a1 += xk * Ws[k * NF + lane + 32];
    }
#pragma unroll
    for (int k = 0; k < 32; k++) {
        float xk = __shfl_sync(0xffffffffu, v1, k);
        a0 += xk * Ws[(k + 32) * NF + lane];
        a1 += xk * Ws[(k + 32) * NF + lane + 32];
    }

    size_t o = (size_t)row * NF;
    if (mode == 0) {
        g_h[o + lane]      = a0;
        g_h[o + lane + 32] = a1;
        g_agg[o + lane]      = 0.0f;
        g_agg[o + lane + 32] = 0.0f;
    } else {
        float x0 = g_x[o + lane] + a0;
        float x1 = g_x[o + lane + 32] + a1;
        // numerically-stable softplus: max(x,0) + log1p(exp(-|x|))
        g_x[o + lane]      = fmaxf(x0, 0.0f) + log1pf(expf(-fabsf(x0)));
        g_x[o + lane + 32] = fmaxf(x1, 0.0f) + log1pf(expf(-fabsf(x1)));
    }
}

// one warp per edge: f = e@We+be on the fly, m = h[src]*f, atomic scatter to agg[dst]
__global__ void k_edge(const int* __restrict__ src, const int* __restrict__ dst,
                       const float* __restrict__ We, const float* __restrict__ be) {
    __shared__ float Wes[NRBF * NF];
    __shared__ float bes[NF];
    int tid = threadIdx.x;
    for (int i = tid; i < NRBF * NF; i += blockDim.x) Wes[i] = We[i];
    if (tid < NF) bes[tid] = be[tid];
    __syncthreads();

    int wid = tid >> 5, lane = tid & 31;
    int e = blockIdx.x * (blockDim.x >> 5) + wid;
    if (e >= NE) return;

    int s = src[e];
    int d = dst[e];

    float ev = (lane < NRBF) ? g_e[(size_t)e * NRBF + lane] : 0.0f;

    float f0 = bes[lane], f1 = bes[lane + 32];
#pragma unroll
    for (int r = 0; r < NRBF; r++) {
        float er = __shfl_sync(0xffffffffu, ev, r);
        f0 += er * Wes[r * NF + lane];
        f1 += er * Wes[r * NF + lane + 32];
    }

    size_t so = (size_t)s * NF;
    float h0 = __ldg(g_h + so + lane);
    float h1 = __ldg(g_h + so + lane + 32);

    size_t dof = (size_t)d * NF;
    atomicAdd(&g_agg[dof + lane],      h0 * f0);
    atomicAdd(&g_agg[dof + lane + 32], h1 * f1);
}

__global__ void k_zero_pool() {
    int t = blockIdx.x * blockDim.x + threadIdx.x;
    if (t < NG * NF) g_gsum[t] = 0.0f;
    if (t < NG) g_gcnt[t] = 0.0f;
}

// warp per node: scatter into per-graph sums
__global__ void k_pool(const int* __restrict__ batch) {
    int tid = threadIdx.x;
    int wid = tid >> 5, lane = tid & 31;
    int node = blockIdx.x * (blockDim.x >> 5) + wid;
    if (node >= NN) return;
    int b = batch[node];
    size_t o = (size_t)node * NF;
    atomicAdd(&g_gsum[(size_t)b * NF + lane],      g_x[o + lane]);
    atomicAdd(&g_gsum[(size_t)b * NF + lane + 32], g_x[o + lane + 32]);
    if (lane == 0) atomicAdd(&g_gcnt[b], 1.0f);
}

// one block (128 threads) per graph: mean -> relu(c@Ws+bs) -> two 2-layer heads
__global__ void k_head(const float* __restrict__ Wsm, const float* __restrict__ bsm,
                       const float* __restrict__ Wbg1, const float* __restrict__ bbg1,
                       const float* __restrict__ Wbg2, const float* __restrict__ bbg2,
                       const float* __restrict__ Weh1, const float* __restrict__ beh1,
                       const float* __restrict__ Weh2, const float* __restrict__ beh2,
                       float* __restrict__ out) {
    __shared__ float cs[NF];
    __shared__ float c2[2 * NH];
    __shared__ float red[128];

    int g = blockIdx.x, t = threadIdx.x;

    if (t < NF) {
        float cnt = fmaxf(g_gcnt[g], 1.0f);
        cs[t] = g_gsum[(size_t)g * NF + t] / cnt;
    }
    __syncthreads();

    {   // c2 = relu(c @ Ws + bs)  -> [128]
        float acc = bsm[t];
#pragma unroll 8
        for (int k = 0; k < NF; k++) acc += cs[k] * Wsm[k * 128 + t];
        c2[t] = fmaxf(acc, 0.0f);
    }
    __syncthreads();

    float partial;
    if (t < NH) {
        float acc = bbg1[t];
#pragma unroll 8
        for (int k = 0; k < 2 * NH; k++) acc += c2[k] * Wbg1[k * NH + t];
        partial = fmaxf(acc, 0.0f) * Wbg2[t];
    } else {
        int j = t - NH;
        float acc = beh1[j];
#pragma unroll 8
        for (int k = 0; k < 2 * NH; k++) acc += c2[k] * Weh1[k * NH + j];
        partial = fmaxf(acc, 0.0f) * Weh2[j];
    }
    red[t] = partial;
    __syncthreads();

    int base = t & 64;
    int l = t & 63;
#pragma unroll
    for (int s = 32; s > 0; s >>= 1) {
        if (l < s) red[base + l] += red[base + l + s];
        __syncthreads();
    }
    if (t == 0)  out[g]      = red[0]  + bbg2[0];
    if (t == 64) out[NG + g] = red[64] + beh2[0];
}

// ---------------- launch ----------------
extern "C" void kernel_launch(void* const* d_in, const int* in_sizes, int n_in,
                              void* d_out, int out_size) {
    const int*   x_ids = (const int*)d_in[0];
    const int*   eidx  = (const int*)d_in[1];
    const float* ea    = (const float*)d_in[2];
    const int*   batch = (const int*)d_in[3];
    const float* emb   = (const float*)d_in[4];
    const float* W1    = (const float*)d_in[5];
    const float* b1    = (const float*)d_in[6];
    const float* We    = (const float*)d_in[7];
    const float* be    = (const float*)d_in[8];
    const float* W2    = (const float*)d_in[9];
    const float* b2    = (const float*)d_in[10];
    const float* Wsm   = (const float*)d_in[11];
    const float* bsm   = (const float*)d_in[12];
    const float* Wbg1  = (const float*)d_in[13];
    const float* bbg1  = (const float*)d_in[14];
    const float* Wbg2  = (const float*)d_in[15];
    const float* bbg2  = (const float*)d_in[16];
    const float* Weh1  = (const float*)d_in[17];
    const float* beh1  = (const float*)d_in[18];
    const float* Weh2  = (const float*)d_in[19];
    const float* beh2  = (const float*)d_in[20];

    const int* src = eidx;
    const int* dst = eidx + NE;
    float* out = (float*)d_out;

    k_embed<<<(NN * NF + 255) / 256, 256>>>(x_ids, emb);
    k_rbf<<<(NE + 255) / 256, 256>>>(ea);

    for (int i = 0; i < 3; i++) {
        k_node_gemm<<<(NN + 7) / 8, 256>>>(W1 + i * NF * NF, b1 + i * NF, 0);
        k_edge<<<(NE + 7) / 8, 256>>>(src, dst, We + i * NRBF * NF, be + i * NF);
        k_node_gemm<<<(NN + 7) / 8, 256>>>(W2 + i * NF * NF, b2 + i * NF, 1);
    }

    k_zero_pool<<<(NG * NF + 255) / 256, 256>>>();
    k_pool<<<(NN + 7) / 8, 256>>>(batch);
    k_head<<<NG, 128>>>(Wsm, bsm, Wbg1, bbg1, Wbg2, bbg2, Weh1, beh1, Weh2, beh2, out);
}

// round 2
// speedup vs baseline: 2.0401x; 2.0401x over previous
#include <cuda_runtime.h>
#include <math.h>

#define NN   50000
#define NE   800000
#define NF   64
#define NRBF 10
#define NG   512
#define NH   64

// ---------------- scratch (device globals, float4 for 16B alignment) ----------------
__device__ float4 g_x4[NN * 16];      // node features
__device__ float4 g_h4[NN * 16];      // pre-message transform
__device__ float4 g_agg4[NN * 16];    // scatter accumulator
__device__ float4 g_gsum4[NG * 16];   // per-graph sums
__device__ float  g_gcnt[NG];         // per-graph counts

__device__ __forceinline__ void red_add_v4(float* p, float4 v) {
    asm volatile("red.global.add.v4.f32 [%0], {%1,%2,%3,%4};"
                 :: "l"(p), "f"(v.x), "f"(v.y), "f"(v.z), "f"(v.w) : "memory");
}
__device__ __forceinline__ float4 f4add(float4 a, float4 b) {
    return make_float4(a.x + b.x, a.y + b.y, a.z + b.z, a.w + b.w);
}
__device__ __forceinline__ float4 f4fma(float s, float4 w, float4 a) {
    return make_float4(fmaf(s, w.x, a.x), fmaf(s, w.y, a.y),
                       fmaf(s, w.z, a.z), fmaf(s, w.w, a.w));
}
__device__ __forceinline__ float4 f4mul(float4 a, float4 b) {
    return make_float4(a.x * b.x, a.y * b.y, a.z * b.z, a.w * b.w);
}

// ---------------- kernels ----------------

// x[n, :] = emb[x_ids[n], :]   (float4 rows)
__global__ void k_embed(const int* __restrict__ ids, const float4* __restrict__ emb4) {
    int t = blockIdx.x * blockDim.x + threadIdx.x;
    if (t >= NN * 16) return;
    g_x4[t] = emb4[ids[t >> 4] * 16 + (t & 15)];
}

// mode 0: g_h = g_x @ W + b   (also zeroes g_agg)
// mode 1: g_x = softplus(g_x + g_agg @ W + b)
// block: 256 threads = 32 rows x (8 threads/row, 8 cols/thread)
__global__ void k_node_gemm(const float* __restrict__ W, const float* __restrict__ b, int mode) {
    __shared__ float4 Ws4[NF * 16];   // W[64][64] row-major as float4
    __shared__ float4 xs4[32 * 16];   // 32 input rows
    __shared__ float  bs[NF];

    int t = threadIdx.x;
    const float4* W4 = (const float4*)W;
#pragma unroll
    for (int i = 0; i < 4; i++) Ws4[t + 256 * i] = W4[t + 256 * i];
    if (t < NF) bs[t] = b[t];

    int rowbase = blockIdx.x * 32;
    const float4* in4 = mode ? g_agg4 : g_x4;
    // cooperative load of 32 input rows (512 float4)
#pragma unroll
    for (int i = 0; i < 2; i++) {
        int idx = t + 256 * i;                // [0,512)
        int r = rowbase + (idx >> 4);
        if (r < NN) xs4[idx] = in4[(size_t)r * 16 + (idx & 15)];
    }
    __syncthreads();

    int rl  = t >> 3;            // local row 0..31
    int row = rowbase + rl;
    if (row >= NN) return;
    int cg  = t & 7;             // col group: cols cg*8 .. cg*8+7

    float4 a0 = make_float4(bs[cg * 8 + 0], bs[cg * 8 + 1], bs[cg * 8 + 2], bs[cg * 8 + 3]);
    float4 a1 = make_float4(bs[cg * 8 + 4], bs[cg * 8 + 5], bs[cg * 8 + 6], bs[cg * 8 + 7]);

#pragma unroll
    for (int k4 = 0; k4 < 16; k4++) {
        float4 xv = xs4[rl * 16 + k4];
        int kb = k4 * 4;
        float4 w;
        w = Ws4[(kb + 0) * 16 + cg * 2];     a0 = f4fma(xv.x, w, a0);
        w = Ws4[(kb + 0) * 16 + cg * 2 + 1]; a1 = f4fma(xv.x, w, a1);
        w = Ws4[(kb + 1) * 16 + cg * 2];     a0 = f4fma(xv.y, w, a0);
        w = Ws4[(kb + 1) * 16 + cg * 2 + 1]; a1 = f4fma(xv.y, w, a1);
        w = Ws4[(kb + 2) * 16 + cg * 2];     a0 = f4fma(xv.z, w, a0);
        w = Ws4[(kb + 2) * 16 + cg * 2 + 1]; a1 = f4fma(xv.z, w, a1);
        w = Ws4[(kb + 3) * 16 + cg * 2];     a0 = f4fma(xv.w, w, a0);
        w = Ws4[(kb + 3) * 16 + cg * 2 + 1]; a1 = f4fma(xv.w, w, a1);
    }

    size_t o = (size_t)row * 16 + cg * 2;
    if (mode == 0) {
        g_h4[o]     = a0;
        g_h4[o + 1] = a1;
        g_agg4[o]     = make_float4(0.f, 0.f, 0.f, 0.f);
        g_agg4[o + 1] = make_float4(0.f, 0.f, 0.f, 0.f);
    } else {
        float4 x0 = f4add(g_x4[o], a0);
        float4 x1 = f4add(g_x4[o + 1], a1);
        // stable softplus
        x0.x = fmaxf(x0.x, 0.f) + log1pf(expf(-fabsf(x0.x)));
        x0.y = fmaxf(x0.y, 0.f) + log1pf(expf(-fabsf(x0.y)));
        x0.z = fmaxf(x0.z, 0.f) + log1pf(expf(-fabsf(x0.z)));
        x0.w = fmaxf(x0.w, 0.f) + log1pf(expf(-fabsf(x0.w)));
        x1.x = fmaxf(x1.x, 0.f) + log1pf(expf(-fabsf(x1.x)));
        x1.y = fmaxf(x1.y, 0.f) + log1pf(expf(-fabsf(x1.y)));
        x1.z = fmaxf(x1.z, 0.f) + log1pf(expf(-fabsf(x1.z)));
        x1.w = fmaxf(x1.w, 0.f) + log1pf(expf(-fabsf(x1.w)));
        g_x4[o]     = x0;
        g_x4[o + 1] = x1;
    }
}

// 16 lanes per edge, float4 per lane: RBF recomputed in-kernel, f = e@We+be,
// gather h[src] (LDG.128), m = h*f, red.global.add.v4 scatter to agg[dst].
__global__ void k_edge(const int* __restrict__ src, const int* __restrict__ dst,
                       const float* __restrict__ We, const float* __restrict__ be,
                       const float* __restrict__ ea) {
    __shared__ float4 Wf4[NRBF * 16];
    __shared__ float4 bef4[16];
    int t = threadIdx.x;
    if (t < NRBF * 16) Wf4[t] = ((const float4*)We)[t];
    if (t >= NRBF * 16 && t < NRBF * 16 + 16) bef4[t - NRBF * 16] = ((const float4*)be)[t - NRBF * 16];
    __syncthreads();

    int wid = t >> 5, lane = t & 31;
    int sub = lane >> 4;          // edge within warp
    int sl  = lane & 15;          // float4 slot
    int e = blockIdx.x * 16 + wid * 2 + sub;
    if (e >= NE) return;

    int s = src[e];
    int d = dst[e];
    float dist = ea[e];

    // RBF values: lane r (r<10) of each 16-group computes e_r
    float ev = 0.0f;
    if (sl < NRBF) {
        float tt = dist - 0.66666667f * (float)sl;
        ev = expf(-1.125f * tt * tt);
    }

    float4 f = bef4[sl];
#pragma unroll
    for (int r = 0; r < NRBF; r++) {
        float er = __shfl_sync(0xffffffffu, ev, (lane & 16) + r);
        f = f4fma(er, Wf4[r * 16 + sl], f);
    }

    float4 hv = __ldg(g_h4 + (size_t)s * 16 + sl);
    float4 m  = f4mul(hv, f);
    red_add_v4((float*)(g_agg4 + (size_t)d * 16 + sl), m);
}

__global__ void k_zero_pool() {
    int t = blockIdx.x * blockDim.x + threadIdx.x;
    if (t < NG * 16) g_gsum4[t] = make_float4(0.f, 0.f, 0.f, 0.f);
    if (t < NG) g_gcnt[t] = 0.0f;
}

// 16 lanes per node, float4 red scatter into per-graph sums
__global__ void k_pool(const int* __restrict__ batch) {
    int t = threadIdx.x;
    int wid = t >> 5, lane = t & 31;
    int sub = lane >> 4, sl = lane & 15;
    int node = blockIdx.x * 16 + wid * 2 + sub;
    if (node >= NN) return;
    int b = batch[node];
    float4 v = g_x4[(size_t)node * 16 + sl];
    red_add_v4((float*)(g_gsum4 + (size_t)b * 16 + sl), v);
    if (sl == 0) atomicAdd(&g_gcnt[b], 1.0f);
}

// one block (128 threads) per graph
__global__ void k_head(const float* __restrict__ Wsm, const float* __restrict__ bsm,
                       const float* __restrict__ Wbg1, const float* __restrict__ bbg1,
                       const float* __restrict__ Wbg2, const float* __restrict__ bbg2,
                       const float* __restrict__ Weh1, const float* __restrict__ beh1,
                       const float* __restrict__ Weh2, const float* __restrict__ beh2,
                       float* __restrict__ out) {
    __shared__ float cs[NF];
    __shared__ float c2[2 * NH];
    __shared__ float red[128];

    int g = blockIdx.x, t = threadIdx.x;
    const float* gsum = (const float*)g_gsum4;

    if (t < NF) {
        float cnt = fmaxf(g_gcnt[g], 1.0f);
        cs[t] = gsum[(size_t)g * NF + t] / cnt;
    }
    __syncthreads();

    {
        float acc = bsm[t];
#pragma unroll 8
        for (int k = 0; k < NF; k++) acc += cs[k] * Wsm[k * 128 + t];
        c2[t] = fmaxf(acc, 0.0f);
    }
    __syncthreads();

    float partial;
    if (t < NH) {
        float acc = bbg1[t];
#pragma unroll 8
        for (int k = 0; k < 2 * NH; k++) acc += c2[k] * Wbg1[k * NH + t];
        partial = fmaxf(acc, 0.0f) * Wbg2[t];
    } else {
        int j = t - NH;
        float acc = beh1[j];
#pragma unroll 8
        for (int k = 0; k < 2 * NH; k++) acc += c2[k] * Weh1[k * NH + j];
        partial = fmaxf(acc, 0.0f) * Weh2[j];
    }
    red[t] = partial;
    __syncthreads();

    int base = t & 64;
    int l = t & 63;
#pragma unroll
    for (int s = 32; s > 0; s >>= 1) {
        if (l < s) red[base + l] += red[base + l + s];
        __syncthreads();
    }
    if (t == 0)  out[g]      = red[0]  + bbg2[0];
    if (t == 64) out[NG + g] = red[64] + beh2[0];
}

// ---------------- launch ----------------
extern "C" void kernel_launch(void* const* d_in, const int* in_sizes, int n_in,
                              void* d_out, int out_size) {
    const int*   x_ids = (const int*)d_in[0];
    const int*   eidx  = (const int*)d_in[1];
    const float* ea    = (const float*)d_in[2];
    const int*   batch = (const int*)d_in[3];
    const float* emb   = (const float*)d_in[4];
    const float* W1    = (const float*)d_in[5];
    const float* b1    = (const float*)d_in[6];
    const float* We    = (const float*)d_in[7];
    const float* be    = (const float*)d_in[8];
    const float* W2    = (const float*)d_in[9];
    const float* b2    = (const float*)d_in[10];
    const float* Wsm   = (const float*)d_in[11];
    const float* bsm   = (const float*)d_in[12];
    const float* Wbg1  = (const float*)d_in[13];
    const float* bbg1  = (const float*)d_in[14];
    const float* Wbg2  = (const float*)d_in[15];
    const float* bbg2  = (const float*)d_in[16];
    const float* Weh1  = (const float*)d_in[17];
    const float* beh1  = (const float*)d_in[18];
    const float* Weh2  = (const float*)d_in[19];
    const float* beh2  = (const float*)d_in[20];

    const int* src = eidx;
    const int* dst = eidx + NE;
    float* out = (float*)d_out;

    k_embed<<<(NN * 16 + 255) / 256, 256>>>(x_ids, (const float4*)emb);

    for (int i = 0; i < 3; i++) {
        k_node_gemm<<<(NN + 31) / 32, 256>>>(W1 + i * NF * NF, b1 + i * NF, 0);
        k_edge<<<NE / 16, 256>>>(src, dst, We + i * NRBF * NF, be + i * NF, ea);
        k_node_gemm<<<(NN + 31) / 32, 256>>>(W2 + i * NF * NF, b2 + i * NF, 1);
    }

    k_zero_pool<<<(NG * 16 + 255) / 256, 256>>>();
    k_pool<<<(NN + 15) / 16, 256>>>(batch);
    k_head<<<NG, 128>>>(Wsm, bsm, Wbg1, bbg1, Wbg2, bbg2, Weh1, beh1, Weh2, beh2, out);
}

// round 3
// speedup vs baseline: 2.9252x; 1.4339x over previous
#include <cuda_runtime.h>
#include <math.h>

#define NN   50000
#define NE   800000
#define NF   64
#define NRBF 10
#define NG   512
#define NH   64

// ---------------- scratch (device globals) ----------------
__device__ float4 g_x4[NN * 16];      // node features
__device__ float4 g_h4[NN * 16];      // pre-message transform
__device__ float4 g_agg4[NN * 16];    // scatter accumulator
__device__ float4 g_gsum4[NG * 16];   // per-graph sums
__device__ float  g_gcnt[NG];         // per-graph counts

// ---------------- helpers ----------------
__device__ __forceinline__ void red_add_v4(float* p, float4 v) {
    asm volatile("red.global.add.v4.f32 [%0], {%1,%2,%3,%4};"
                 :: "l"(p), "f"(v.x), "f"(v.y), "f"(v.z), "f"(v.w) : "memory");
}
__device__ __forceinline__ void red_add_f(float* p, float v) {
    asm volatile("red.global.add.f32 [%0], %1;" :: "l"(p), "f"(v) : "memory");
}
__device__ __forceinline__ unsigned long long pack2(float x, float y) {
    unsigned long long r;
    asm("mov.b64 %0, {%1,%2};" : "=l"(r) : "f"(x), "f"(y));
    return r;
}
__device__ __forceinline__ void fma2(unsigned long long& d, unsigned long long a, unsigned long long b) {
    asm("fma.rn.f32x2 %0, %1, %2, %3;" : "=l"(d) : "l"(a), "l"(b), "l"(d));
}
__device__ __forceinline__ float2 unpack2(unsigned long long v) {
    float2 f;
    asm("mov.b64 {%0,%1}, %2;" : "=f"(f.x), "=f"(f.y) : "l"(v));
    return f;
}
__device__ __forceinline__ float4 f4fma(float s, float4 w, float4 a) {
    return make_float4(fmaf(s, w.x, a.x), fmaf(s, w.y, a.y),
                       fmaf(s, w.z, a.z), fmaf(s, w.w, a.w));
}
__device__ __forceinline__ float4 f4mul(float4 a, float4 b) {
    return make_float4(a.x * b.x, a.y * b.y, a.z * b.z, a.w * b.w);
}
__device__ __forceinline__ float sp(float x) {   // stable softplus
    return fmaxf(x, 0.0f) + log1pf(expf(-fabsf(x)));
}

// ---------------- node GEMM: 128 rows/block, 256 thr, 4 rows x 8 cols/thread ----------------
// mode 0: g_h = in @ W + b ; zero g_agg.   (if ids != null: in = emb[ids], also writes g_x)
// mode 1: g_x = softplus(g_x + g_agg @ W + b)
// mode 2: like mode 1 but result goes straight to graph pool (g_gsum/g_gcnt), g_x not written
__global__ __launch_bounds__(256) void k_node_gemm(
        const float* __restrict__ W, const float* __restrict__ b, int mode,
        const int* __restrict__ ids, const float4* __restrict__ emb4,
        const int* __restrict__ batch) {
    __shared__ float4 Ws4[NF * 16];        // W[64][64] as float4
    __shared__ float4 xs4[128 * 17];       // 128 input rows, padded stride 17
    __shared__ float  bs[NF];

    int t = threadIdx.x;
    const float4* W4 = (const float4*)W;
#pragma unroll
    for (int i = 0; i < 4; i++) Ws4[t + 256 * i] = W4[t + 256 * i];
    if (t < NF) bs[t] = b[t];

    int rowbase = blockIdx.x * 128;
    const float4* in4 = (mode == 0) ? g_x4 : g_agg4;

    // cooperative load of 128 input rows (2048 float4), 8 per thread
#pragma unroll
    for (int i = 0; i < 8; i++) {
        int idx = t + 256 * i;
        int lr = idx >> 4, c = idx & 15;
        int row = rowbase + lr;
        if (row < NN) {
            float4 v;
            if (ids) {                      // fused embedding gather (conv0 mode0)
                v = emb4[(size_t)ids[row] * 16 + c];
                g_x4[(size_t)row * 16 + c] = v;
            } else {
                v = in4[(size_t)row * 16 + c];
            }
            xs4[lr * 17 + c] = v;
        }
    }
    __syncthreads();

    int cg = t & 7;              // col group: cols cg*8 .. cg*8+7
    int rl = t >> 3;             // base local row 0..31; rows rl+32*i

    // accumulators: 4 rows x 4 f32x2 pairs (8 cols)
    unsigned long long a[4][4];
    {
        int cb = cg * 8;
        unsigned long long b0 = pack2(bs[cb + 0], bs[cb + 1]);
        unsigned long long b1 = pack2(bs[cb + 2], bs[cb + 3]);
        unsigned long long b2 = pack2(bs[cb + 4], bs[cb + 5]);
        unsigned long long b3 = pack2(bs[cb + 6], bs[cb + 7]);
#pragma unroll
        for (int i = 0; i < 4; i++) { a[i][0] = b0; a[i][1] = b1; a[i][2] = b2; a[i][3] = b3; }
    }

#pragma unroll 4
    for (int k4 = 0; k4 < 16; k4++) {
        float4 xv[4];
#pragma unroll
        for (int i = 0; i < 4; i++) xv[i] = xs4[(rl + 32 * i) * 17 + k4];
#pragma unroll
        for (int sub = 0; sub < 4; sub++) {
            int k = k4 * 4 + sub;
            const ulonglong2* wp = (const ulonglong2*)(Ws4 + k * 16 + cg * 2);
            ulonglong2 wA = wp[0];           // cols 0-3 of this thread's 8
            ulonglong2 wB = wp[1];           // cols 4-7
#pragma unroll
            for (int i = 0; i < 4; i++) {
                float xk = (sub == 0) ? xv[i].x : (sub == 1) ? xv[i].y : (sub == 2) ? xv[i].z : xv[i].w;
                unsigned long long s = pack2(xk, xk);
                fma2(a[i][0], s, wA.x);
                fma2(a[i][1], s, wA.y);
                fma2(a[i][2], s, wB.x);
                fma2(a[i][3], s, wB.y);
            }
        }
    }

#pragma unroll
    for (int i = 0; i < 4; i++) {
        int row = rowbase + rl + 32 * i;
        if (row >= NN) continue;
        float2 p0 = unpack2(a[i][0]), p1 = unpack2(a[i][1]);
        float2 p2 = unpack2(a[i][2]), p3 = unpack2(a[i][3]);
        float4 r0 = make_float4(p0.x, p0.y, p1.x, p1.y);
        float4 r1 = make_float4(p2.x, p2.y, p3.x, p3.y);
        size_t o = (size_t)row * 16 + cg * 2;
        if (mode == 0) {
            g_h4[o]     = r0;
            g_h4[o + 1] = r1;
            g_agg4[o]     = make_float4(0.f, 0.f, 0.f, 0.f);
            g_agg4[o + 1] = make_float4(0.f, 0.f, 0.f, 0.f);
        } else {
            float4 x0 = g_x4[o], x1 = g_x4[o + 1];
            x0 = make_float4(sp(x0.x + r0.x), sp(x0.y + r0.y), sp(x0.z + r0.z), sp(x0.w + r0.w));
            x1 = make_float4(sp(x1.x + r1.x), sp(x1.y + r1.y), sp(x1.z + r1.z), sp(x1.w + r1.w));
            if (mode == 1) {
                g_x4[o]     = x0;
                g_x4[o + 1] = x1;
            } else {                         // mode 2: fused graph mean-pool scatter
                int bg = batch[row];
                red_add_v4((float*)(g_gsum4 + (size_t)bg * 16 + cg * 2), x0);
                red_add_v4((float*)(g_gsum4 + (size_t)bg * 16 + cg * 2 + 1), x1);
                if (cg == 0) red_add_f(&g_gcnt[bg], 1.0f);
            }
        }
    }
}

// ---------------- edge kernel: 16 lanes/edge, float4 per lane ----------------
__global__ void k_edge(const int* __restrict__ src, const int* __restrict__ dst,
                       const float* __restrict__ We, const float* __restrict__ be,
                       const float* __restrict__ ea) {
    __shared__ float4 Wf4[NRBF * 16];
    __shared__ float4 bef4[16];
    int t = threadIdx.x;
    if (t < NRBF * 16) Wf4[t] = ((const float4*)We)[t];
    if (t >= NRBF * 16 && t < NRBF * 16 + 16) bef4[t - NRBF * 16] = ((const float4*)be)[t - NRBF * 16];
    __syncthreads();

    int wid = t >> 5, lane = t & 31;
    int sub = lane >> 4;          // edge within warp
    int sl  = lane & 15;          // float4 slot
    int e = blockIdx.x * 16 + wid * 2 + sub;
    if (e >= NE) return;

    int s = src[e];
    int d = dst[e];
    float dist = ea[e];

    float ev = 0.0f;
    if (sl < NRBF) {
        float tt = dist - 0.66666667f * (float)sl;
        ev = expf(-1.125f * tt * tt);
    }

    float4 f = bef4[sl];
#pragma unroll
    for (int r = 0; r < NRBF; r++) {
        float er = __shfl_sync(0xffffffffu, ev, (lane & 16) + r);
        f = f4fma(er, Wf4[r * 16 + sl], f);
    }

    float4 hv = __ldg(g_h4 + (size_t)s * 16 + sl);
    float4 m  = f4mul(hv, f);
    red_add_v4((float*)(g_agg4 + (size_t)d * 16 + sl), m);
}

__global__ void k_zero_pool() {
    int t = blockIdx.x * blockDim.x + threadIdx.x;
    if (t < NG * 16) g_gsum4[t] = make_float4(0.f, 0.f, 0.f, 0.f);
    if (t < NG) g_gcnt[t] = 0.0f;
}

// ---------------- head: one block (128 threads) per graph ----------------
__global__ void k_head(const float* __restrict__ Wsm, const float* __restrict__ bsm,
                       const float* __restrict__ Wbg1, const float* __restrict__ bbg1,
                       const float* __restrict__ Wbg2, const float* __restrict__ bbg2,
                       const float* __restrict__ Weh1, const float* __restrict__ beh1,
                       const float* __restrict__ Weh2, const float* __restrict__ beh2,
                       float* __restrict__ out) {
    __shared__ float cs[NF];
    __shared__ float c2[2 * NH];
    __shared__ float red[128];

    int g = blockIdx.x, t = threadIdx.x;
    const float* gsum = (const float*)g_gsum4;

    if (t < NF) {
        float cnt = fmaxf(g_gcnt[g], 1.0f);
        cs[t] = gsum[(size_t)g * NF + t] / cnt;
    }
    __syncthreads();

    {
        float acc = bsm[t];
#pragma unroll 8
        for (int k = 0; k < NF; k++) acc += cs[k] * Wsm[k * 128 + t];
        c2[t] = fmaxf(acc, 0.0f);
    }
    __syncthreads();

    float partial;
    if (t < NH) {
        float acc = bbg1[t];
#pragma unroll 8
        for (int k = 0; k < 2 * NH; k++) acc += c2[k] * Wbg1[k * NH + t];
        partial = fmaxf(acc, 0.0f) * Wbg2[t];
    } else {
        int j = t - NH;
        float acc = beh1[j];
#pragma unroll 8
        for (int k = 0; k < 2 * NH; k++) acc += c2[k] * Weh1[k * NH + j];
        partial = fmaxf(acc, 0.0f) * Weh2[j];
    }
    red[t] = partial;
    __syncthreads();

    int base = t & 64;
    int l = t & 63;
#pragma unroll
    for (int s = 32; s > 0; s >>= 1) {
        if (l < s) red[base + l] += red[base + l + s];
        __syncthreads();
    }
    if (t == 0)  out[g]      = red[0]  + bbg2[0];
    if (t == 64) out[NG + g] = red[64] + beh2[0];
}

// ---------------- launch ----------------
extern "C" void kernel_launch(void* const* d_in, const int* in_sizes, int n_in,
                              void* d_out, int out_size) {
    const int*   x_ids = (const int*)d_in[0];
    const int*   eidx  = (const int*)d_in[1];
    const float* ea    = (const float*)d_in[2];
    const int*   batch = (const int*)d_in[3];
    const float* emb   = (const float*)d_in[4];
    const float* W1    = (const float*)d_in[5];
    const float* b1    = (const float*)d_in[6];
    const float* We    = (const float*)d_in[7];
    const float* be    = (const float*)d_in[8];
    const float* W2    = (const float*)d_in[9];
    const float* b2    = (const float*)d_in[10];
    const float* Wsm   = (const float*)d_in[11];
    const float* bsm   = (const float*)d_in[12];
    const float* Wbg1  = (const float*)d_in[13];
    const float* bbg1  = (const float*)d_in[14];
    const float* Wbg2  = (const float*)d_in[15];
    const float* bbg2  = (const float*)d_in[16];
    const float* Weh1  = (const float*)d_in[17];
    const float* beh1  = (const float*)d_in[18];
    const float* Weh2  = (const float*)d_in[19];
    const float* beh2  = (const float*)d_in[20];

    const int* src = eidx;
    const int* dst = eidx + NE;
    float* out = (float*)d_out;

    const int GB = (NN + 127) / 128;

    k_zero_pool<<<(NG * 16 + 255) / 256, 256>>>();

    for (int i = 0; i < 3; i++) {
        k_node_gemm<<<GB, 256>>>(W1 + i * NF * NF, b1 + i * NF, 0,
                                 (i == 0) ? x_ids : nullptr, (const float4*)emb, nullptr);
        k_edge<<<NE / 16, 256>>>(src, dst, We + i * NRBF * NF, be + i * NF, ea);
        k_node_gemm<<<GB, 256>>>(W2 + i * NF * NF, b2 + i * NF, (i == 2) ? 2 : 1,
                                 nullptr, nullptr, batch);
    }

    k_head<<<NG, 128>>>(Wsm, bsm, Wbg1, bbg1, Wbg2, bbg2, Weh1, beh1, Weh2, beh2, out);
}